// round 11
// baseline (speedup 1.0000x reference)
#include <cuda_runtime.h>
#include <cuda_bf16.h>
#include <cstdint>

// Problem constants (fixed by setup_inputs)
#define BB 2
#define LL 2048
#define SSS 2048
#define HH 8
#define EE 64

#define BT 64        // L and S tile
#define NTHREADS 128 // 4 warps; warp w owns rows 16w..16w+15

#define PADK 68      // K smem stride (floats): b-frag banks = lane (conflict-free)
#define PADV 72      // V smem stride: b-frag banks = 8*tig+gid (conflict-free)
#define PADP 68      // P smem stride: a-frag banks = 4*gid+tig (conflict-free)

#define MASK_SCALE 10000.0f
#define NEG_BIG (-1e30f)
#define SCALE 0.125f  // 1/sqrt(64), exact power of two

// Precomputed additive mask: madd[h,l,s] = (hard==0) ? NEG_BIG
//                                        : SCALE * 10000 * min(sig-thr, 0)
__device__ float g_madd[HH * LL * SSS];
// K/V pre-rounded to tf32 and transposed to [b][h][s][e]
__device__ float g_kt[BB * HH * SSS * EE];
__device__ float g_vt[BB * HH * SSS * EE];

// ---------------------------------------------------------------------------
// helpers
// ---------------------------------------------------------------------------
__device__ __forceinline__ float tf32r(float x) {
    float y;
    asm("cvt.rna.tf32.f32 %0, %1;" : "=f"(y) : "f"(x));
    return y;
}

__device__ __forceinline__ void mma_tf32(float c[4], const uint32_t a[4],
                                         const uint32_t bfr[2]) {
    asm volatile(
        "mma.sync.aligned.m16n8k8.row.col.f32.tf32.tf32.f32 "
        "{%0,%1,%2,%3}, {%4,%5,%6,%7}, {%8,%9}, {%0,%1,%2,%3};"
        : "+f"(c[0]), "+f"(c[1]), "+f"(c[2]), "+f"(c[3])
        : "r"(a[0]), "r"(a[1]), "r"(a[2]), "r"(a[3]),
          "r"(bfr[0]), "r"(bfr[1]));
}

__device__ __forceinline__ uint32_t smem_u32(const void* p) {
    return (uint32_t)__cvta_generic_to_shared(p);
}

__device__ __forceinline__ void cp_async16(uint32_t dst, const void* src) {
    asm volatile("cp.async.cg.shared.global [%0], [%1], 16;" :: "r"(dst), "l"(src));
}

#define CP_COMMIT() asm volatile("cp.async.commit_group;")
#define CP_WAIT1()  asm volatile("cp.async.wait_group 1;")
#define CP_WAIT2()  asm volatile("cp.async.wait_group 2;")

// ---------------------------------------------------------------------------
// Kernel 0: round K/V to tf32 once, transpose (b,s,h,e) -> (b,h,s,e)
// ---------------------------------------------------------------------------
__global__ __launch_bounds__(256)
void preround_kv_kernel(const float* __restrict__ kk,
                        const float* __restrict__ vv_)
{
    const int i = (blockIdx.x * 256 + threadIdx.x) * 4;  // linear (b,s,h,e)
    const int e  = i & (EE - 1);
    const int t  = i >> 6;           // b*S*H + s*H + h
    const int h  = t & (HH - 1);
    const int t2 = t >> 3;           // b*S + s
    const int s  = t2 & (SSS - 1);
    const int b  = t2 >> 11;

    const float4 k4 = *(const float4*)&kk[i];
    const float4 v4 = *(const float4*)&vv_[i];
    const int o = (((b * HH + h) * SSS) + s) * EE + e;
    float4 ko, vo;
    ko.x = tf32r(k4.x); ko.y = tf32r(k4.y); ko.z = tf32r(k4.z); ko.w = tf32r(k4.w);
    vo.x = tf32r(v4.x); vo.y = tf32r(v4.y); vo.z = tf32r(v4.z); vo.w = tf32r(v4.w);
    *(float4*)&g_kt[o] = ko;
    *(float4*)&g_vt[o] = vo;
}

// ---------------------------------------------------------------------------
// Kernel 1: precompute the DAG + hard-mask additive term (memory/MUFU-bound)
// ---------------------------------------------------------------------------
__global__ __launch_bounds__(256)
void precompute_madd_kernel(const float* __restrict__ phi,
                            const float* __restrict__ uu_,
                            const int*   __restrict__ hard,
                            const float* __restrict__ log_tau,
                            const float* __restrict__ threshold,
                            const int*   __restrict__ causal_flag)
{
    const int row = blockIdx.y;          // h*LL + l
    const int l   = row & (LL - 1);
    const int s   = (blockIdx.x * 256 + threadIdx.x) * 4;
    if (causal_flag[0] && s > l) return;   // upper triangle never read (causal)

    float tau = __expf(log_tau[0]);
    tau = fminf(fmaxf(tau, 0.1f), 5.0f);
    const float inv_tau = 1.0f / tau;
    float thr = threshold[0];
    thr = fminf(fmaxf(thr, 0.01f), 0.99f);

    const int idx = row * SSS + s;
    const float4 ph = *(const float4*)&phi[idx];
    const float4 uv = *(const float4*)&uu_[idx];
    const int4   hm = *(const int4*)&hard[l * SSS + s];

    float4 o;
    {
        float g = __logf(__fdividef(uv.x + 1e-8f, 1.0f - uv.x + 1e-8f));
        float sg = __fdividef(1.0f, 1.0f + __expf(-(g + ph.x) * inv_tau));
        o.x = hm.x == 0 ? NEG_BIG : SCALE * MASK_SCALE * fminf(sg - thr, 0.0f);
    }
    {
        float g = __logf(__fdividef(uv.y + 1e-8f, 1.0f - uv.y + 1e-8f));
        float sg = __fdividef(1.0f, 1.0f + __expf(-(g + ph.y) * inv_tau));
        o.y = hm.y == 0 ? NEG_BIG : SCALE * MASK_SCALE * fminf(sg - thr, 0.0f);
    }
    {
        float g = __logf(__fdividef(uv.z + 1e-8f, 1.0f - uv.z + 1e-8f));
        float sg = __fdividef(1.0f, 1.0f + __expf(-(g + ph.z) * inv_tau));
        o.z = hm.z == 0 ? NEG_BIG : SCALE * MASK_SCALE * fminf(sg - thr, 0.0f);
    }
    {
        float g = __logf(__fdividef(uv.w + 1e-8f, 1.0f - uv.w + 1e-8f));
        float sg = __fdividef(1.0f, 1.0f + __expf(-(g + ph.w) * inv_tau));
        o.w = hm.w == 0 ? NEG_BIG : SCALE * MASK_SCALE * fminf(sg - thr, 0.0f);
    }
    *(float4*)&g_madd[idx] = o;
}

// ---------------------------------------------------------------------------
// Kernel 2: flash attention on tensor cores (tf32 mma.sync m16n8k8).
// K double-buffered (cp.async), V single-buffered (separate commit groups),
// K/V pre-rounded to tf32 (no cvt in mainloop). 3 CTAs/SM.
//
// Fragment layouts (lane = gid*4 + tig):
//   A (16x8 row):  a0=(gid,tig) a1=(gid+8,tig) a2=(gid,tig+4) a3=(gid+8,tig+4)
//   B (8x8 col):   b0=(k=tig,n=gid) b1=(k=tig+4,n=gid)
//   C (16x8):      c0=(gid,2tig) c1=(gid,2tig+1) c2=(gid+8,2tig) c3=(gid+8,2tig+1)
// ---------------------------------------------------------------------------
__global__ __launch_bounds__(NTHREADS, 3)
void phi_softmax_mma_kernel(const float* __restrict__ q,
                            const int*   __restrict__ causal_flag,
                            float*       __restrict__ out)
{
    extern __shared__ float smem[];
    float* Ks = smem;                             // [2][64][PADK]
    float* Vs = Ks + 2 * BT * PADK;               // [64][PADV] (single buffer)
    float* Ps = Vs + BT * PADV;                   // [64][PADP]

    const int b  = blockIdx.x;                    // batch fastest -> madd L2 reuse
    const int h  = blockIdx.y;
    const int lt = gridDim.z - 1 - blockIdx.z;    // heavy tiles first
    const int l0 = lt * BT;

    const int tid  = threadIdx.x;
    const int w    = tid >> 5;
    const int lane = tid & 31;
    const int gid  = lane >> 2;
    const int tig  = lane & 3;

    const int r0 = 16 * w + gid;                  // this thread's two rows
    const int r1 = r0 + 8;
    const int lg0 = l0 + r0;
    const int lg1 = l0 + r1;

    const int causal = causal_flag[0];
    const int nst = causal ? (lt + 1) : (SSS / BT);

    const float* kt = g_kt + (b * HH + h) * (SSS * EE);
    const float* vt = g_vt + (b * HH + h) * (SSS * EE);

    // per-thread cp.async slice: 8 chunks of 16B
    const int cr  = tid >> 4;           // base row (advance by 8)
    const int cec = (tid & 15) * 4;     // e column

    // ---- prologue: K(0) then V(0), separate groups ----
    #pragma unroll
    for (int c = 0; c < 8; c++) {
        const int r = cr + 8 * c;
        cp_async16(smem_u32(&Ks[r * PADK + cec]), &kt[r * EE + cec]);
    }
    CP_COMMIT();   // group: K0
    #pragma unroll
    for (int c = 0; c < 8; c++) {
        const int r = cr + 8 * c;
        cp_async16(smem_u32(&Vs[r * PADV + cec]), &vt[r * EE + cec]);
    }
    CP_COMMIT();   // group: V0

    // ---- stage scaled Q into Ps, then load Q a-frags into registers ----
    for (int i = tid; i < BT * (EE / 4); i += NTHREADS) {
        int r  = i >> 4;
        int ec = (i & 15) * 4;
        float4 q4 = *(const float4*)&q[((b * LL + l0 + r) * HH + h) * EE + ec];
        Ps[r * PADP + ec + 0] = q4.x * SCALE;
        Ps[r * PADP + ec + 1] = q4.y * SCALE;
        Ps[r * PADP + ec + 2] = q4.z * SCALE;
        Ps[r * PADP + ec + 3] = q4.w * SCALE;
    }
    __syncthreads();

    uint32_t qa[8][4];                            // full K-dim of Q, tf32
    #pragma unroll
    for (int k8 = 0; k8 < 8; k8++) {
        qa[k8][0] = __float_as_uint(tf32r(Ps[r0 * PADP + 8 * k8 + tig]));
        qa[k8][1] = __float_as_uint(tf32r(Ps[r1 * PADP + 8 * k8 + tig]));
        qa[k8][2] = __float_as_uint(tf32r(Ps[r0 * PADP + 8 * k8 + tig + 4]));
        qa[k8][3] = __float_as_uint(tf32r(Ps[r1 * PADP + 8 * k8 + tig + 4]));
    }

    float o[8][4];
    float mrun0 = NEG_BIG, mrun1 = NEG_BIG, lrun0 = 0.0f, lrun1 = 0.0f;
    #pragma unroll
    for (int n = 0; n < 8; n++)
        #pragma unroll
        for (int j = 0; j < 4; j++) o[n][j] = 0.0f;

    const float* maddR0 = g_madd + (h * LL + lg0) * SSS;
    const float* maddR1 = g_madd + (h * LL + lg1) * SSS;

    for (int st = 0; st < nst; st++) {
        const int s0 = st * BT;
        const float* Kb = Ks + (st & 1) * BT * PADK;

        // ---- issue K(st+1) (buffer last read by GEMM1(st-1); safe after
        //      the post-GEMM2 barrier of iter st-1) ----
        if (st + 1 < nst) {
            float* Kn = Ks + ((st + 1) & 1) * BT * PADK;
            const float* ksrc = kt + (s0 + BT) * EE;
            #pragma unroll
            for (int c = 0; c < 8; c++) {
                const int r = cr + 8 * c;
                cp_async16(smem_u32(&Kn[r * PADK + cec]), &ksrc[r * EE + cec]);
            }
        }
        CP_COMMIT();   // group K(st+1) (possibly empty)

        CP_WAIT2();    // K(st) resident (V(st), K(st+1) may still fly)
        __syncthreads();   // K(st) visible to all warps; all warps done with Ps(st-1)

        // ---- prefetch madd for this tile (overlaps GEMM1) ----
        float2 ma0[8], ma1[8];
        #pragma unroll
        for (int n = 0; n < 8; n++) {
            const int sc = s0 + 8 * n + 2 * tig;
            ma0[n] = *(const float2*)&maddR0[sc];
            ma1[n] = *(const float2*)&maddR1[sc];
        }

        // ---- GEMM1: scores (pre-scaled by SCALE via Q; K already tf32) ----
        float cc[8][4];
        #pragma unroll
        for (int n = 0; n < 8; n++)
            #pragma unroll
            for (int j = 0; j < 4; j++) cc[n][j] = 0.0f;

        #pragma unroll
        for (int n = 0; n < 8; n++) {
            const uint32_t* krow = (const uint32_t*)(Kb + (8 * n + gid) * PADK);
            #pragma unroll
            for (int k8 = 0; k8 < 8; k8++) {
                uint32_t bf[2];
                bf[0] = krow[8 * k8 + tig];
                bf[1] = krow[8 * k8 + tig + 4];
                mma_tf32(cc[n], qa[k8], bf);
            }
        }

        // ---- additive mask + causal + online softmax ----
        float rmax0 = NEG_BIG, rmax1 = NEG_BIG;
        #pragma unroll
        for (int n = 0; n < 8; n++) {
            const int sc = s0 + 8 * n + 2 * tig;
            float x0 = cc[n][0] + ma0[n].x;
            float x1 = cc[n][1] + ma0[n].y;
            float x2 = cc[n][2] + ma1[n].x;
            float x3 = cc[n][3] + ma1[n].y;
            if (causal) {
                if (sc     > lg0) x0 = NEG_BIG;
                if (sc + 1 > lg0) x1 = NEG_BIG;
                if (sc     > lg1) x2 = NEG_BIG;
                if (sc + 1 > lg1) x3 = NEG_BIG;
            }
            cc[n][0] = x0; cc[n][1] = x1; cc[n][2] = x2; cc[n][3] = x3;
            rmax0 = fmaxf(rmax0, fmaxf(x0, x1));
            rmax1 = fmaxf(rmax1, fmaxf(x2, x3));
        }
        rmax0 = fmaxf(rmax0, __shfl_xor_sync(0xffffffffu, rmax0, 1, 4));
        rmax0 = fmaxf(rmax0, __shfl_xor_sync(0xffffffffu, rmax0, 2, 4));
        rmax1 = fmaxf(rmax1, __shfl_xor_sync(0xffffffffu, rmax1, 1, 4));
        rmax1 = fmaxf(rmax1, __shfl_xor_sync(0xffffffffu, rmax1, 2, 4));

        const float mnew0 = fmaxf(mrun0, rmax0);
        const float mnew1 = fmaxf(mrun1, rmax1);
        const float al0 = __expf(mrun0 - mnew0);
        const float al1 = __expf(mrun1 - mnew1);
        mrun0 = mnew0; mrun1 = mnew1;

        float ls0 = 0.0f, ls1 = 0.0f;
        #pragma unroll
        for (int n = 0; n < 8; n++) {
            // Fully-masked-so-far rows give p=1 garbage; annihilated once the
            // first real entry (open diagonal) makes alpha=exp(-inf)=0.
            float p0 = __expf(cc[n][0] - mnew0);
            float p1 = __expf(cc[n][1] - mnew0);
            float p2 = __expf(cc[n][2] - mnew1);
            float p3 = __expf(cc[n][3] - mnew1);
            ls0 += p0 + p1;
            ls1 += p2 + p3;
            const int pc = 8 * n + 2 * tig;
            *(float2*)&Ps[r0 * PADP + pc] = make_float2(tf32r(p0), tf32r(p1));
            *(float2*)&Ps[r1 * PADP + pc] = make_float2(tf32r(p2), tf32r(p3));
        }
        lrun0 = lrun0 * al0 + ls0;
        lrun1 = lrun1 * al1 + ls1;
        #pragma unroll
        for (int n = 0; n < 8; n++) {
            o[n][0] *= al0; o[n][1] *= al0;
            o[n][2] *= al1; o[n][3] *= al1;
        }
        __syncwarp();   // P rows are warp-private; order STS before LDS

        CP_WAIT1();        // V(st) resident (only K(st+1) still pending)
        __syncthreads();   // V visible to all warps

        // ---- GEMM2: out += P @ V (V already tf32) ----
        #pragma unroll
        for (int k8 = 0; k8 < 8; k8++) {
            uint32_t pa[4];
            const uint32_t* Pu = (const uint32_t*)Ps;
            pa[0] = Pu[r0 * PADP + 8 * k8 + tig];
            pa[1] = Pu[r1 * PADP + 8 * k8 + tig];
            pa[2] = Pu[r0 * PADP + 8 * k8 + tig + 4];
            pa[3] = Pu[r1 * PADP + 8 * k8 + tig + 4];
            const uint32_t* v0 = (const uint32_t*)(Vs + (8 * k8 + tig) * PADV);
            const uint32_t* v1 = (const uint32_t*)(Vs + (8 * k8 + tig + 4) * PADV);
            #pragma unroll
            for (int n = 0; n < 8; n++) {
                uint32_t vb[2];
                vb[0] = v0[8 * n + gid];
                vb[1] = v1[8 * n + gid];
                mma_tf32(o[n], pa, vb);
            }
        }

        __syncthreads();   // all warps done reading V before refill

        // ---- issue V(st+1) into the single V buffer ----
        if (st + 1 < nst) {
            const float* vsrc = vt + (s0 + BT) * EE;
            #pragma unroll
            for (int c = 0; c < 8; c++) {
                const int r = cr + 8 * c;
                cp_async16(smem_u32(&Vs[r * PADV + cec]), &vsrc[r * EE + cec]);
            }
        }
        CP_COMMIT();   // group V(st+1) (possibly empty)
    }

    // ---- finalize: reduce row sums across quad, normalize, store ----
    lrun0 += __shfl_xor_sync(0xffffffffu, lrun0, 1, 4);
    lrun0 += __shfl_xor_sync(0xffffffffu, lrun0, 2, 4);
    lrun1 += __shfl_xor_sync(0xffffffffu, lrun1, 1, 4);
    lrun1 += __shfl_xor_sync(0xffffffffu, lrun1, 2, 4);
    const float inv0 = 1.0f / lrun0;   // diagonal always open -> lrun > 0
    const float inv1 = 1.0f / lrun1;

    float* out0 = out + ((b * LL + lg0) * HH + h) * EE;
    float* out1 = out + ((b * LL + lg1) * HH + h) * EE;
    #pragma unroll
    for (int n = 0; n < 8; n++) {
        const int ec = 8 * n + 2 * tig;
        *(float2*)&out0[ec] = make_float2(o[n][0] * inv0, o[n][1] * inv0);
        *(float2*)&out1[ec] = make_float2(o[n][2] * inv1, o[n][3] * inv1);
    }
}

extern "C" void kernel_launch(void* const* d_in, const int* in_sizes, int n_in,
                              void* d_out, int out_size)
{
    const float* q        = (const float*)d_in[0];
    const float* k        = (const float*)d_in[1];
    const float* v        = (const float*)d_in[2];
    const int*   causal   = (const int*)d_in[6];
    const int*   hard     = (const int*)d_in[7];
    const float* phi      = (const float*)d_in[8];
    const float* log_tau  = (const float*)d_in[9];
    const float* thr      = (const float*)d_in[10];
    const float* u        = (const float*)d_in[11];
    float* out            = (float*)d_out;

    // Kernel 0: pre-round K/V to tf32, transpose to [b][h][s][e]
    {
        const int n4 = BB * SSS * HH * EE / 4;
        preround_kv_kernel<<<n4 / 256, 256>>>(k, v);
    }

    // Kernel 1: precompute additive mask (batch-independent)
    {
        dim3 grid(SSS / (256 * 4), HH * LL);
        precompute_madd_kernel<<<grid, 256>>>(phi, u, hard, log_tau, thr, causal);
    }

    // Kernel 2: pipelined tensor-core attention
    {
        const int smem_bytes =
            (2 * BT * PADK + BT * PADV + BT * PADP) * sizeof(float);
        cudaFuncSetAttribute(phi_softmax_mma_kernel,
                             cudaFuncAttributeMaxDynamicSharedMemorySize, smem_bytes);
        dim3 grid(BB, HH, LL / BT);
        phi_softmax_mma_kernel<<<grid, NTHREADS, smem_bytes>>>(q, causal, out);
    }
}

// round 12
// speedup vs baseline: 1.1143x; 1.1143x over previous
#include <cuda_runtime.h>
#include <cuda_bf16.h>
#include <cstdint>

// Problem constants (fixed by setup_inputs)
#define BB 2
#define LL 2048
#define SSS 2048
#define HH 8
#define EE 64

#define BT 64        // L and S tile
#define NTHREADS 128 // 4 warps; warp w owns rows 16w..16w+15

#define PADK 68      // K smem stride (floats): b-frag banks conflict-free
#define PADV 72      // V smem stride: b-frag banks conflict-free
#define PADP 68      // P smem stride: a-frag banks conflict-free

#define MASK_SCALE 10000.0f
#define NEG_BIG (-1e30f)
#define SCALE 0.125f  // 1/sqrt(64), exact power of two

// Precomputed additive mask: madd[h,l,s] = (hard==0) ? NEG_BIG
//                                        : SCALE * 10000 * min(sig-thr, 0)
__device__ float g_madd[HH * LL * SSS];
// K/V pre-rounded to tf32 and transposed to [b][h][s][e]
__device__ float g_kt[BB * HH * SSS * EE];
__device__ float g_vt[BB * HH * SSS * EE];

// ---------------------------------------------------------------------------
// helpers
// ---------------------------------------------------------------------------
__device__ __forceinline__ float tf32r(float x) {
    float y;
    asm("cvt.rna.tf32.f32 %0, %1;" : "=f"(y) : "f"(x));
    return y;
}

__device__ __forceinline__ void mma_tf32(float c[4], const uint32_t a[4],
                                         const uint32_t bfr[2]) {
    asm volatile(
        "mma.sync.aligned.m16n8k8.row.col.f32.tf32.tf32.f32 "
        "{%0,%1,%2,%3}, {%4,%5,%6,%7}, {%8,%9}, {%0,%1,%2,%3};"
        : "+f"(c[0]), "+f"(c[1]), "+f"(c[2]), "+f"(c[3])
        : "r"(a[0]), "r"(a[1]), "r"(a[2]), "r"(a[3]),
          "r"(bfr[0]), "r"(bfr[1]));
}

__device__ __forceinline__ uint32_t smem_u32(const void* p) {
    return (uint32_t)__cvta_generic_to_shared(p);
}

__device__ __forceinline__ void cp_async16(uint32_t dst, const void* src) {
    asm volatile("cp.async.cg.shared.global [%0], [%1], 16;" :: "r"(dst), "l"(src));
}

#define CP_COMMIT() asm volatile("cp.async.commit_group;")
#define CP_WAIT1()  asm volatile("cp.async.wait_group 1;")

// ---------------------------------------------------------------------------
// Kernel 0: round K/V to tf32 once, transpose (b,s,h,e) -> (b,h,s,e)
// ---------------------------------------------------------------------------
__global__ __launch_bounds__(256)
void preround_kv_kernel(const float* __restrict__ kk,
                        const float* __restrict__ vv_)
{
    const int i = (blockIdx.x * 256 + threadIdx.x) * 4;  // linear (b,s,h,e)
    const int e  = i & (EE - 1);
    const int t  = i >> 6;           // b*S*H + s*H + h
    const int h  = t & (HH - 1);
    const int t2 = t >> 3;           // b*S + s
    const int s  = t2 & (SSS - 1);
    const int b  = t2 >> 11;

    const float4 k4 = *(const float4*)&kk[i];
    const float4 v4 = *(const float4*)&vv_[i];
    const int o = (((b * HH + h) * SSS) + s) * EE + e;
    float4 ko, vo;
    ko.x = tf32r(k4.x); ko.y = tf32r(k4.y); ko.z = tf32r(k4.z); ko.w = tf32r(k4.w);
    vo.x = tf32r(v4.x); vo.y = tf32r(v4.y); vo.z = tf32r(v4.z); vo.w = tf32r(v4.w);
    *(float4*)&g_kt[o] = ko;
    *(float4*)&g_vt[o] = vo;
}

// ---------------------------------------------------------------------------
// Kernel 1: precompute the DAG + hard-mask additive term (memory/MUFU-bound)
// ---------------------------------------------------------------------------
__global__ __launch_bounds__(256)
void precompute_madd_kernel(const float* __restrict__ phi,
                            const float* __restrict__ uu_,
                            const int*   __restrict__ hard,
                            const float* __restrict__ log_tau,
                            const float* __restrict__ threshold,
                            const int*   __restrict__ causal_flag)
{
    const int row = blockIdx.y;          // h*LL + l
    const int l   = row & (LL - 1);
    const int s   = (blockIdx.x * 256 + threadIdx.x) * 4;
    if (causal_flag[0] && s > l) return;   // upper triangle never read (causal)

    float tau = __expf(log_tau[0]);
    tau = fminf(fmaxf(tau, 0.1f), 5.0f);
    const float inv_tau = 1.0f / tau;
    float thr = threshold[0];
    thr = fminf(fmaxf(thr, 0.01f), 0.99f);

    const int idx = row * SSS + s;
    const float4 ph = *(const float4*)&phi[idx];
    const float4 uv = *(const float4*)&uu_[idx];
    const int4   hm = *(const int4*)&hard[l * SSS + s];

    float4 o;
    {
        float g = __logf(__fdividef(uv.x + 1e-8f, 1.0f - uv.x + 1e-8f));
        float sg = __fdividef(1.0f, 1.0f + __expf(-(g + ph.x) * inv_tau));
        o.x = hm.x == 0 ? NEG_BIG : SCALE * MASK_SCALE * fminf(sg - thr, 0.0f);
    }
    {
        float g = __logf(__fdividef(uv.y + 1e-8f, 1.0f - uv.y + 1e-8f));
        float sg = __fdividef(1.0f, 1.0f + __expf(-(g + ph.y) * inv_tau));
        o.y = hm.y == 0 ? NEG_BIG : SCALE * MASK_SCALE * fminf(sg - thr, 0.0f);
    }
    {
        float g = __logf(__fdividef(uv.z + 1e-8f, 1.0f - uv.z + 1e-8f));
        float sg = __fdividef(1.0f, 1.0f + __expf(-(g + ph.z) * inv_tau));
        o.z = hm.z == 0 ? NEG_BIG : SCALE * MASK_SCALE * fminf(sg - thr, 0.0f);
    }
    {
        float g = __logf(__fdividef(uv.w + 1e-8f, 1.0f - uv.w + 1e-8f));
        float sg = __fdividef(1.0f, 1.0f + __expf(-(g + ph.w) * inv_tau));
        o.w = hm.w == 0 ? NEG_BIG : SCALE * MASK_SCALE * fminf(sg - thr, 0.0f);
    }
    *(float4*)&g_madd[idx] = o;
}

// ---------------------------------------------------------------------------
// Kernel 2: flash attention on tensor cores (tf32 mma.sync m16n8k8).
// R9 pipeline shape (K AND V double-buffered, one commit group per tile,
// single wait point) + pre-rounded K/V (no cvt in the mainloop).
//
// Fragment layouts (lane = gid*4 + tig):
//   A (16x8 row):  a0=(gid,tig) a1=(gid+8,tig) a2=(gid,tig+4) a3=(gid+8,tig+4)
//   B (8x8 col):   b0=(k=tig,n=gid) b1=(k=tig+4,n=gid)
//   C (16x8):      c0=(gid,2tig) c1=(gid,2tig+1) c2=(gid+8,2tig) c3=(gid+8,2tig+1)
// ---------------------------------------------------------------------------
__global__ __launch_bounds__(NTHREADS)
void phi_softmax_mma_kernel(const float* __restrict__ q,
                            const int*   __restrict__ causal_flag,
                            float*       __restrict__ out)
{
    extern __shared__ float smem[];
    float* Ks = smem;                             // [2][64][PADK]
    float* Vs = Ks + 2 * BT * PADK;               // [2][64][PADV]
    float* Ps = Vs + 2 * BT * PADV;               // [64][PADP]

    const int b  = blockIdx.x;                    // batch fastest -> madd L2 reuse
    const int h  = blockIdx.y;
    const int lt = gridDim.z - 1 - blockIdx.z;    // heavy tiles first
    const int l0 = lt * BT;

    const int tid  = threadIdx.x;
    const int w    = tid >> 5;
    const int lane = tid & 31;
    const int gid  = lane >> 2;
    const int tig  = lane & 3;

    const int r0 = 16 * w + gid;                  // this thread's two rows
    const int r1 = r0 + 8;
    const int lg0 = l0 + r0;
    const int lg1 = l0 + r1;

    const int causal = causal_flag[0];
    const int nst = causal ? (lt + 1) : (SSS / BT);

    const float* kt = g_kt + (b * HH + h) * (SSS * EE);
    const float* vt = g_vt + (b * HH + h) * (SSS * EE);

    // per-thread cp.async slice: 8 chunks of 16B for K, 8 for V
    const int cr  = tid >> 4;           // base row (advance by 8)
    const int cec = (tid & 15) * 4;     // e column

    // ---- prologue: issue tile 0 loads (one group: K0+V0) ----
    #pragma unroll
    for (int c = 0; c < 8; c++) {
        const int r = cr + 8 * c;
        cp_async16(smem_u32(&Ks[r * PADK + cec]), &kt[r * EE + cec]);
        cp_async16(smem_u32(&Vs[r * PADV + cec]), &vt[r * EE + cec]);
    }
    CP_COMMIT();

    // ---- stage scaled Q into Ps, then load Q a-frags into registers ----
    for (int i = tid; i < BT * (EE / 4); i += NTHREADS) {
        int r  = i >> 4;
        int ec = (i & 15) * 4;
        float4 q4 = *(const float4*)&q[((b * LL + l0 + r) * HH + h) * EE + ec];
        Ps[r * PADP + ec + 0] = q4.x * SCALE;
        Ps[r * PADP + ec + 1] = q4.y * SCALE;
        Ps[r * PADP + ec + 2] = q4.z * SCALE;
        Ps[r * PADP + ec + 3] = q4.w * SCALE;
    }
    __syncthreads();

    uint32_t qa[8][4];                            // full K-dim of Q, tf32
    #pragma unroll
    for (int k8 = 0; k8 < 8; k8++) {
        qa[k8][0] = __float_as_uint(tf32r(Ps[r0 * PADP + 8 * k8 + tig]));
        qa[k8][1] = __float_as_uint(tf32r(Ps[r1 * PADP + 8 * k8 + tig]));
        qa[k8][2] = __float_as_uint(tf32r(Ps[r0 * PADP + 8 * k8 + tig + 4]));
        qa[k8][3] = __float_as_uint(tf32r(Ps[r1 * PADP + 8 * k8 + tig + 4]));
    }

    float o[8][4];
    float mrun0 = NEG_BIG, mrun1 = NEG_BIG, lrun0 = 0.0f, lrun1 = 0.0f;
    #pragma unroll
    for (int n = 0; n < 8; n++)
        #pragma unroll
        for (int j = 0; j < 4; j++) o[n][j] = 0.0f;

    const float* maddR0 = g_madd + (h * LL + lg0) * SSS;
    const float* maddR1 = g_madd + (h * LL + lg1) * SSS;

    for (int st = 0; st < nst; st++) {
        const int s0 = st * BT;
        const float* Kb = Ks + (st & 1) * BT * PADK;
        const float* Vb = Vs + (st & 1) * BT * PADV;

        // all warps done with previous iteration (incl. GEMM2 reads of the
        // buffer we are about to refill, and Ps reads before softmax rewrites)
        __syncthreads();

        // ---- issue next tile's cp.async (empty group keeps wait uniform) ----
        if (st + 1 < nst) {
            float* Kn = Ks + ((st + 1) & 1) * BT * PADK;
            float* Vn = Vs + ((st + 1) & 1) * BT * PADV;
            const float* ksrc = kt + (s0 + BT) * EE;
            const float* vsrc = vt + (s0 + BT) * EE;
            #pragma unroll
            for (int c = 0; c < 8; c++) {
                const int r = cr + 8 * c;
                cp_async16(smem_u32(&Kn[r * PADK + cec]), &ksrc[r * EE + cec]);
                cp_async16(smem_u32(&Vn[r * PADV + cec]), &vsrc[r * EE + cec]);
            }
        }
        CP_COMMIT();
        CP_WAIT1();        // tile st resident; tile st+1 still in flight
        __syncthreads();

        // ---- prefetch madd for this tile into registers (overlaps GEMM1) ----
        float2 ma0[8], ma1[8];
        #pragma unroll
        for (int n = 0; n < 8; n++) {
            const int sc = s0 + 8 * n + 2 * tig;
            ma0[n] = *(const float2*)&maddR0[sc];
            ma1[n] = *(const float2*)&maddR1[sc];
        }

        // ---- GEMM1: scores (pre-scaled by SCALE via Q; K already tf32) ----
        float cc[8][4];
        #pragma unroll
        for (int n = 0; n < 8; n++)
            #pragma unroll
            for (int j = 0; j < 4; j++) cc[n][j] = 0.0f;

        #pragma unroll
        for (int n = 0; n < 8; n++) {
            const uint32_t* krow = (const uint32_t*)(Kb + (8 * n + gid) * PADK);
            #pragma unroll
            for (int k8 = 0; k8 < 8; k8++) {
                uint32_t bf[2];
                bf[0] = krow[8 * k8 + tig];
                bf[1] = krow[8 * k8 + tig + 4];
                mma_tf32(cc[n], qa[k8], bf);
            }
        }

        // ---- additive mask + causal + online softmax ----
        float rmax0 = NEG_BIG, rmax1 = NEG_BIG;
        #pragma unroll
        for (int n = 0; n < 8; n++) {
            const int sc = s0 + 8 * n + 2 * tig;
            float x0 = cc[n][0] + ma0[n].x;
            float x1 = cc[n][1] + ma0[n].y;
            float x2 = cc[n][2] + ma1[n].x;
            float x3 = cc[n][3] + ma1[n].y;
            if (causal) {
                if (sc     > lg0) x0 = NEG_BIG;
                if (sc + 1 > lg0) x1 = NEG_BIG;
                if (sc     > lg1) x2 = NEG_BIG;
                if (sc + 1 > lg1) x3 = NEG_BIG;
            }
            cc[n][0] = x0; cc[n][1] = x1; cc[n][2] = x2; cc[n][3] = x3;
            rmax0 = fmaxf(rmax0, fmaxf(x0, x1));
            rmax1 = fmaxf(rmax1, fmaxf(x2, x3));
        }
        rmax0 = fmaxf(rmax0, __shfl_xor_sync(0xffffffffu, rmax0, 1, 4));
        rmax0 = fmaxf(rmax0, __shfl_xor_sync(0xffffffffu, rmax0, 2, 4));
        rmax1 = fmaxf(rmax1, __shfl_xor_sync(0xffffffffu, rmax1, 1, 4));
        rmax1 = fmaxf(rmax1, __shfl_xor_sync(0xffffffffu, rmax1, 2, 4));

        const float mnew0 = fmaxf(mrun0, rmax0);
        const float mnew1 = fmaxf(mrun1, rmax1);
        const float al0 = __expf(mrun0 - mnew0);
        const float al1 = __expf(mrun1 - mnew1);
        mrun0 = mnew0; mrun1 = mnew1;

        float ls0 = 0.0f, ls1 = 0.0f;
        #pragma unroll
        for (int n = 0; n < 8; n++) {
            // Fully-masked-so-far rows give p=1 garbage; annihilated once the
            // first real entry (open diagonal) makes alpha=exp(-inf)=0.
            float p0 = __expf(cc[n][0] - mnew0);
            float p1 = __expf(cc[n][1] - mnew0);
            float p2 = __expf(cc[n][2] - mnew1);
            float p3 = __expf(cc[n][3] - mnew1);
            ls0 += p0 + p1;
            ls1 += p2 + p3;
            const int pc = 8 * n + 2 * tig;
            *(float2*)&Ps[r0 * PADP + pc] = make_float2(tf32r(p0), tf32r(p1));
            *(float2*)&Ps[r1 * PADP + pc] = make_float2(tf32r(p2), tf32r(p3));
        }
        lrun0 = lrun0 * al0 + ls0;
        lrun1 = lrun1 * al1 + ls1;
        #pragma unroll
        for (int n = 0; n < 8; n++) {
            o[n][0] *= al0; o[n][1] *= al0;
            o[n][2] *= al1; o[n][3] *= al1;
        }
        __syncwarp();   // P rows are warp-private; order STS before LDS

        // ---- GEMM2: out += P @ V (V already tf32) ----
        #pragma unroll
        for (int k8 = 0; k8 < 8; k8++) {
            uint32_t pa[4];
            const uint32_t* Pu = (const uint32_t*)Ps;
            pa[0] = Pu[r0 * PADP + 8 * k8 + tig];
            pa[1] = Pu[r1 * PADP + 8 * k8 + tig];
            pa[2] = Pu[r0 * PADP + 8 * k8 + tig + 4];
            pa[3] = Pu[r1 * PADP + 8 * k8 + tig + 4];
            const uint32_t* v0 = (const uint32_t*)(Vb + (8 * k8 + tig) * PADV);
            const uint32_t* v1 = (const uint32_t*)(Vb + (8 * k8 + tig + 4) * PADV);
            #pragma unroll
            for (int n = 0; n < 8; n++) {
                uint32_t vb[2];
                vb[0] = v0[8 * n + gid];
                vb[1] = v1[8 * n + gid];
                mma_tf32(o[n], pa, vb);
            }
        }
    }

    // ---- finalize: reduce row sums across quad, normalize, store ----
    lrun0 += __shfl_xor_sync(0xffffffffu, lrun0, 1, 4);
    lrun0 += __shfl_xor_sync(0xffffffffu, lrun0, 2, 4);
    lrun1 += __shfl_xor_sync(0xffffffffu, lrun1, 1, 4);
    lrun1 += __shfl_xor_sync(0xffffffffu, lrun1, 2, 4);
    const float inv0 = 1.0f / lrun0;   // diagonal always open -> lrun > 0
    const float inv1 = 1.0f / lrun1;

    float* out0 = out + ((b * LL + lg0) * HH + h) * EE;
    float* out1 = out + ((b * LL + lg1) * HH + h) * EE;
    #pragma unroll
    for (int n = 0; n < 8; n++) {
        const int ec = 8 * n + 2 * tig;
        *(float2*)&out0[ec] = make_float2(o[n][0] * inv0, o[n][1] * inv0);
        *(float2*)&out1[ec] = make_float2(o[n][2] * inv1, o[n][3] * inv1);
    }
}

extern "C" void kernel_launch(void* const* d_in, const int* in_sizes, int n_in,
                              void* d_out, int out_size)
{
    const float* q        = (const float*)d_in[0];
    const float* k        = (const float*)d_in[1];
    const float* v        = (const float*)d_in[2];
    const int*   causal   = (const int*)d_in[6];
    const int*   hard     = (const int*)d_in[7];
    const float* phi      = (const float*)d_in[8];
    const float* log_tau  = (const float*)d_in[9];
    const float* thr      = (const float*)d_in[10];
    const float* u        = (const float*)d_in[11];
    float* out            = (float*)d_out;

    // Kernel 0: pre-round K/V to tf32, transpose to [b][h][s][e]
    {
        const int n4 = BB * SSS * HH * EE / 4;
        preround_kv_kernel<<<n4 / 256, 256>>>(k, v);
    }

    // Kernel 1: precompute additive mask (batch-independent)
    {
        dim3 grid(SSS / (256 * 4), HH * LL);
        precompute_madd_kernel<<<grid, 256>>>(phi, u, hard, log_tau, thr, causal);
    }

    // Kernel 2: pipelined tensor-core attention (R9 pipeline shape)
    {
        const int smem_bytes =
            (2 * BT * PADK + 2 * BT * PADV + BT * PADP) * sizeof(float);
        cudaFuncSetAttribute(phi_softmax_mma_kernel,
                             cudaFuncAttributeMaxDynamicSharedMemorySize, smem_bytes);
        dim3 grid(BB, HH, LL / BT);
        phi_softmax_mma_kernel<<<grid, NTHREADS, smem_bytes>>>(q, causal, out);
    }
}